// round 4
// baseline (speedup 1.0000x reference)
#include <cuda_runtime.h>

// Pooling_83141976916902: out[g, c] = sum_{i : batch[i]==g} x[i, c]
// (softmax over a size-1 axis == 1.0, so W/b are dead inputs)
//
// x:     [N, 128] float32   (d_in[0])
// batch: [N]      int64/int32, SORTED, values in [0, G)  (d_in[1])
// out:   [G, 128] float32
//
// Strategy: batch is sorted => each segment is a contiguous row range.
//  Pass A: scatter segment start indices into g_seg_start[] (device global).
//  Pass B: one 128-thread block per segment; 4 warps stream the rows
//          (lane = float4 of 4 channels), smem cross-warp reduce, one
//          coalesced 512B STG per output row. No atomics, no zero pass.

#define C 128
#define MAX_SEGS (1 << 21)  // 2M segments max (8 MB static scratch)

__device__ int g_seg_start[MAX_SEGS + 1];

// Per-thread dtype probe: highest ODD 32-bit word of the batch buffer.
// int64 (values < 2^31): odd words are high halves -> 0.
// int32: that word is a sorted segment id near the end (~G-1) -> nonzero.
__device__ __forceinline__ int batch_stride_words(const int* bw, int n_batch) {
    int idx = ((n_batch - 1) & 1) ? (n_batch - 1) : (n_batch - 2);
    if (idx < 0) idx = 0;
    return (__ldg(&bw[idx]) == 0) ? 2 : 1;  // words per element
}

// Pass A: segment boundary scatter.
// Thread i: for g in (batch[i-1], batch[i]], seg_start[g] = i.
// Thread 0 covers [0, batch[0]]; thread n-1 covers (batch[n-1], G].
__global__ __launch_bounds__(256)
void boundaries_kernel(const int* __restrict__ bw, int n, int G) {
    const int stride = batch_stride_words(bw, n);
    int i = blockIdx.x * blockDim.x + threadIdx.x;
    if (i >= n) return;
    const int cur = bw[(size_t)i * stride];
    const int prev = (i == 0) ? -1 : bw[(size_t)(i - 1) * stride];
    for (int g = prev + 1; g <= cur; g++) g_seg_start[g] = i;
    if (i == n - 1) {
        for (int g = cur + 1; g <= G; g++) g_seg_start[g] = n;
    }
}

// Pass B: one block per segment. Warp w handles rows start+w, start+w+4, ...
// Lane l accumulates channels [4l, 4l+4) as float4; rows are 512B coalesced
// streaming loads. Cross-warp reduce through smem, then one plain store.
__global__ __launch_bounds__(128)
void segsum_seg_kernel(const float4* __restrict__ x4,
                       float4* __restrict__ out, int G) {
    const int g = blockIdx.x;
    if (g >= G) return;
    const int warp = threadIdx.x >> 5;
    const int lane = threadIdx.x & 31;

    const int start = g_seg_start[g];
    const int end = g_seg_start[g + 1];

    float4 acc = make_float4(0.f, 0.f, 0.f, 0.f);

    // 2-deep front-batched stream (independent LDG.128 pairs)
    int r = start + warp;
    for (; r + 4 < end; r += 8) {
        const float4 v0 = __ldcs(&x4[(size_t)r * (C / 4) + lane]);
        const float4 v1 = __ldcs(&x4[(size_t)(r + 4) * (C / 4) + lane]);
        acc.x += v0.x + v1.x;
        acc.y += v0.y + v1.y;
        acc.z += v0.z + v1.z;
        acc.w += v0.w + v1.w;
    }
    if (r < end) {
        const float4 v = __ldcs(&x4[(size_t)r * (C / 4) + lane]);
        acc.x += v.x;
        acc.y += v.y;
        acc.z += v.z;
        acc.w += v.w;
    }

    __shared__ float4 red[4][32];
    red[warp][lane] = acc;
    __syncthreads();

    if (warp == 0) {
        float4 a = red[0][lane];
        const float4 b = red[1][lane];
        const float4 c = red[2][lane];
        const float4 d = red[3][lane];
        a.x += b.x + c.x + d.x;
        a.y += b.y + c.y + d.y;
        a.z += b.z + c.z + d.z;
        a.w += b.w + c.w + d.w;
        out[(size_t)g * (C / 4) + lane] = a;  // empty segment -> zeros
    }
}

extern "C" void kernel_launch(void* const* d_in, const int* in_sizes, int n_in,
                              void* d_out, int out_size) {
    const float* x = (const float*)d_in[0];
    const int* batch_words = (const int*)d_in[1];
    (void)n_in;

    const int n_rows = in_sizes[1];   // N
    const int G = out_size / C;       // number of segments

    {
        int threads = 256;
        int blocks = (n_rows + threads - 1) / threads;
        boundaries_kernel<<<blocks, threads>>>(batch_words, n_rows, G);
    }
    {
        segsum_seg_kernel<<<G, 128>>>((const float4*)x, (float4*)d_out, G);
    }
}